// round 1
// baseline (speedup 1.0000x reference)
#include <cuda_runtime.h>
#include <math.h>

#define NB 4096
#define NSUP 5
#define NROWS (NB + NSUP)   // 4101
#define ED 128
#define DM 256
#define DI 512
#define LH 512
#define G4 2048
#define PADI 200000
#define MAXK 64
#define TOPK 10

// ------------------- device scratch (static, allocation-free) -------------------
__device__ float g_vec[NROWS * DM];     // query_vec rows 0..4095, support_vec rows 4096..4100
__device__ float g_h1[NROWS * DI];      // SE hidden
__device__ float g_enc[NROWS * DM];     // SE output (post-LN)
__device__ float g_supg[DM];            // support_g
__device__ float g_rpart[G4];           // support_g @ Whh[:,256:].T
__device__ float g_bsum[G4];            // b_ih + b_hh
__device__ float g_xpart[(size_t)NB * G4];
__device__ float g_gates[(size_t)NB * G4];
__device__ float g_h[(size_t)NB * DM];
__device__ float g_c[(size_t)NB * LH];
__device__ float g_gcnWt[DM * ED];      // gcn_w_w transposed: [k][d]

__device__ __forceinline__ float warp_sum(float v) {
#pragma unroll
    for (int o = 16; o; o >>= 1) v += __shfl_xor_sync(0xffffffffu, v, o);
    return v;
}
__device__ __forceinline__ float sigf(float x) { return 1.0f / (1.0f + expf(-x)); }

// ------------------- prep: transpose gcn W, sum biases -------------------
__global__ void prep_kernel(const float* __restrict__ gcn_w_w,
                            const float* __restrict__ b_ih,
                            const float* __restrict__ b_hh) {
    int t = threadIdx.x;
    if (blockIdx.x < 128) {
        int d = blockIdx.x;
        g_gcnWt[t * ED + d] = gcn_w_w[d * DM + t];
    } else {
        int n = (blockIdx.x - 128) * 256 + t;
        g_bsum[n] = b_ih[n] + b_hh[n];
    }
}

// ------------------- neighbor encoder: one block per row -------------------
__global__ void __launch_bounds__(128)
neighbor_kernel(const int* __restrict__ qry, const int* __restrict__ sup,
                const int* __restrict__ q_l1, const int* __restrict__ q_deg_l,
                const int* __restrict__ q_r1, const int* __restrict__ q_deg_r,
                const int* __restrict__ s_l1, const int* __restrict__ s_deg_l,
                const int* __restrict__ s_r1, const int* __restrict__ s_deg_r,
                const float* __restrict__ emb,
                const float* __restrict__ gcn_w_b, const float* __restrict__ gcn_b,
                const float* __restrict__ g1_w, const float* __restrict__ g1_b,
                const float* __restrict__ ln1_g, const float* __restrict__ ln1_b,
                const float* __restrict__ g2_w, const float* __restrict__ g2_b,
                const float* __restrict__ gate_temp) {
    __shared__ float s_self[ED], s_selfn[ED];
    __shared__ float s_sim[MAXK];
    __shared__ int s_rel[MAXK], s_ent[MAXK];
    __shared__ int s_sel[TOPK], s_pad[TOPK];
    __shared__ float s_concat[TOPK * DM];
    __shared__ float s_agg[ED];
    __shared__ float s_red[8];
    __shared__ float s_sc[2];
    __shared__ int s_nv;

    int blk = blockIdx.x, tid = threadIdx.x;
    const int* conn;
    int selfid, deg;
    float* out;
    if (blk < NB) {
        int b = blk; conn = q_l1 + b * MAXK * 2; deg = q_deg_l[b];
        selfid = qry[b * 2 + 0]; out = g_vec + (size_t)b * DM;
    } else if (blk < 2 * NB) {
        int b = blk - NB; conn = q_r1 + b * MAXK * 2; deg = q_deg_r[b];
        selfid = qry[b * 2 + 1]; out = g_vec + (size_t)b * DM + ED;
    } else if (blk < 2 * NB + NSUP) {
        int i = blk - 2 * NB; conn = s_l1 + i * MAXK * 2; deg = s_deg_l[i];
        selfid = sup[i * 2 + 0]; out = g_vec + (size_t)(NB + i) * DM;
    } else {
        int i = blk - 2 * NB - NSUP; conn = s_r1 + i * MAXK * 2; deg = s_deg_r[i];
        selfid = sup[i * 2 + 1]; out = g_vec + (size_t)(NB + i) * DM + ED;
    }

    // self embedding + its l2 norm
    float se = emb[(size_t)selfid * ED + tid];
    s_self[tid] = se;
    float ss = warp_sum(se * se);
    if ((tid & 31) == 0) s_red[tid >> 5] = ss;
    __syncthreads();
    if (tid == 0)
        s_sc[0] = 1.0f / fmaxf(sqrtf(s_red[0] + s_red[1] + s_red[2] + s_red[3]), 1e-12f);
    __syncthreads();
    s_selfn[tid] = se * s_sc[0];
    __syncthreads();

    // cosine sims, 4 warps x 16 neighbors
    int warp = tid >> 5, lane = tid & 31;
    float4 sn = ((const float4*)s_selfn)[lane];
    for (int j = warp; j < MAXK; j += 4) {
        int rel = conn[j * 2 + 0];
        int ent = conn[j * 2 + 1];
        float4 e = ((const float4*)(emb + (size_t)ent * ED))[lane];
        float dot = e.x * sn.x + e.y * sn.y + e.z * sn.z + e.w * sn.w;
        float sq = e.x * e.x + e.y * e.y + e.z * e.z + e.w * e.w;
        dot = warp_sum(dot);
        sq = warp_sum(sq);
        if (lane == 0) {
            float sim = dot / fmaxf(sqrtf(sq), 1e-12f);
            if (rel == PADI) sim -= 1e9f;
            s_sim[j] = sim; s_rel[j] = rel; s_ent[j] = ent;
        }
    }
    __syncthreads();

    // top-10 (ties -> lowest index, matching jax.lax.top_k)
    if (tid == 0) {
        float* sv = s_concat;  // scratch
        for (int j = 0; j < MAXK; j++) sv[j] = s_sim[j];
        int nv = 0;
        for (int t = 0; t < TOPK; t++) {
            int bi = 0; float bvv = sv[0];
            for (int j = 1; j < MAXK; j++)
                if (sv[j] > bvv) { bvv = sv[j]; bi = j; }
            sv[bi] = -3.0e38f;
            s_sel[t] = bi;
            int p = (s_rel[bi] == PADI);
            s_pad[t] = p;
            if (!p) nv++;
        }
        s_nv = nv;
    }
    __syncthreads();

    // gather [rel_emb | ent_emb] for the 10 selected neighbors
    for (int t = tid; t < TOPK * DM; t += 128) {
        int j = t >> 8, k = t & 255;
        int id = (k < ED) ? s_rel[s_sel[j]] : s_ent[s_sel[j]];
        s_concat[t] = emb[(size_t)id * ED + (k & (ED - 1))];
    }
    __syncthreads();

    // proj GEMM: only the 10 selected neighbors (ref computes 64, masks 54 away)
    float acc[TOPK];
#pragma unroll
    for (int j = 0; j < TOPK; j++) acc[j] = 0.f;
    for (int k0 = 0; k0 < DM; k0 += 8) {
        float w[8];
#pragma unroll
        for (int i = 0; i < 8; i++) w[i] = g_gcnWt[(k0 + i) * ED + tid];
#pragma unroll
        for (int j = 0; j < TOPK; j++) {
            float4 c0 = *(const float4*)&s_concat[j * DM + k0];
            float4 c1 = *(const float4*)&s_concat[j * DM + k0 + 4];
            acc[j] += c0.x * w[0] + c0.y * w[1] + c0.z * w[2] + c0.w * w[3]
                    + c1.x * w[4] + c1.y * w[5] + c1.z * w[6] + c1.w * w[7];
        }
    }
    float bias = gcn_w_b[tid] + gcn_b[tid];
    float agg = 0.f;
#pragma unroll
    for (int j = 0; j < TOPK; j++) {
        float v = acc[j] + bias;
        v = v > 0.f ? v : 0.01f * v;   // leaky_relu(0.01)
        if (!s_pad[j]) agg += v;
    }
    agg /= fmaxf((float)s_nv, 1.0f);
    s_agg[tid] = agg;
    __syncthreads();

    // gate MLP: 64 = agg @ g1_w.T + b, LN, relu, dot g2
    float y = 0.f;
    if (tid < 64) {
        const float4* wr = (const float4*)(g1_w + tid * ED);
        const float4* ag = (const float4*)s_agg;
#pragma unroll
        for (int k = 0; k < 32; k++) {
            float4 a = ag[k]; float4 w = wr[k];
            y += a.x * w.x + a.y * w.y + a.z * w.z + a.w * w.w;
        }
        y += g1_b[tid];
    }
    float s1 = warp_sum(tid < 64 ? y : 0.f);
    float s2 = warp_sum(tid < 64 ? y * y : 0.f);
    __syncthreads();
    if ((tid & 31) == 0) { s_red[tid >> 5] = s1; s_red[4 + (tid >> 5)] = s2; }
    __syncthreads();
    float S1 = s_red[0] + s_red[1] + s_red[2] + s_red[3];
    float S2 = s_red[4] + s_red[5] + s_red[6] + s_red[7];
    float mean = S1 * (1.0f / 64.0f);
    float var = S2 * (1.0f / 64.0f) - mean * mean;
    float hv = 0.f;
    if (tid < 64) {
        hv = (y - mean) * rsqrtf(var + 1e-5f) * ln1_g[tid] + ln1_b[tid];
        hv = fmaxf(hv, 0.f);
    }
    float lz = warp_sum(tid < 64 ? hv * g2_w[tid] : 0.f);
    __syncthreads();
    if ((tid & 31) == 0) s_red[tid >> 5] = lz;
    __syncthreads();
    if (tid == 0) {
        float logit = s_red[0] + s_red[1] + s_red[2] + s_red[3] + g2_b[0];
        float temp = fminf(fmaxf(gate_temp[0], 0.1f), 5.0f);
        float gate = 1.0f / (1.0f + expf(-logit / temp));
        if (deg <= 0) gate = 0.f;
        s_sc[1] = gate;
    }
    __syncthreads();
    out[tid] = tanhf(s_self[tid] + s_sc[1] * s_agg[tid]);
}

// ------------------- generic tiled fp32 GEMM: C = A(MxK) * W(NxK)^T (+bias)(+rowv)(+base) -------------------
__global__ void __launch_bounds__(256)
gemm_kernel(const float* __restrict__ A, int lda,
            const float* __restrict__ W, int ldw,
            const float* __restrict__ bias,
            const float* __restrict__ base,
            const float* __restrict__ rowv,
            float* __restrict__ C, int ldc,
            int M, int N, int K, int act) {
    __shared__ float As[32][68];
    __shared__ float Ws[32][68];
    int tid = threadIdx.x;
    int m0 = blockIdx.y << 6, n0 = blockIdx.x << 6;
    int lr = tid >> 3;
    int lk = (tid & 7) << 2;
    int tx = tid & 15, ty = tid >> 4;
    float acc[4][4] = {{0.f}};
    for (int k0 = 0; k0 < K; k0 += 32) {
#pragma unroll
        for (int p = 0; p < 2; p++) {
            int m = m0 + lr + p * 32;
            float4 v = make_float4(0.f, 0.f, 0.f, 0.f);
            if (m < M) v = *(const float4*)(A + (size_t)m * lda + k0 + lk);
            As[lk + 0][lr + p * 32] = v.x; As[lk + 1][lr + p * 32] = v.y;
            As[lk + 2][lr + p * 32] = v.z; As[lk + 3][lr + p * 32] = v.w;
            int n = n0 + lr + p * 32;
            float4 wv = *(const float4*)(W + (size_t)n * ldw + k0 + lk);
            Ws[lk + 0][lr + p * 32] = wv.x; Ws[lk + 1][lr + p * 32] = wv.y;
            Ws[lk + 2][lr + p * 32] = wv.z; Ws[lk + 3][lr + p * 32] = wv.w;
        }
        __syncthreads();
#pragma unroll
        for (int kk = 0; kk < 32; kk++) {
            float4 a = *(const float4*)&As[kk][ty << 2];
            float4 w = *(const float4*)&Ws[kk][tx << 2];
            acc[0][0] += a.x * w.x; acc[0][1] += a.x * w.y; acc[0][2] += a.x * w.z; acc[0][3] += a.x * w.w;
            acc[1][0] += a.y * w.x; acc[1][1] += a.y * w.y; acc[1][2] += a.y * w.z; acc[1][3] += a.y * w.w;
            acc[2][0] += a.z * w.x; acc[2][1] += a.z * w.y; acc[2][2] += a.z * w.z; acc[2][3] += a.z * w.w;
            acc[3][0] += a.w * w.x; acc[3][1] += a.w * w.y; acc[3][2] += a.w * w.z; acc[3][3] += a.w * w.w;
        }
        __syncthreads();
    }
#pragma unroll
    for (int i = 0; i < 4; i++) {
        int m = m0 + (ty << 2) + i;
        if (m >= M) continue;
#pragma unroll
        for (int j = 0; j < 4; j++) {
            int n = n0 + (tx << 2) + j;
            float v = acc[i][j];
            if (bias) v += bias[n];
            if (rowv) v += rowv[n];
            if (base) v += base[(size_t)m * ldc + n];
            if (act) v = fmaxf(v, 0.f);
            C[(size_t)m * ldc + n] = v;
        }
    }
}

// ------------------- residual layernorm (support encoder epilogue), in-place on g_enc -------------------
__global__ void __launch_bounds__(256)
ln_kernel(const float* __restrict__ g, const float* __restrict__ b) {
    __shared__ float s_red[16];
    int r = blockIdx.x, t = threadIdx.x;
    float v = g_enc[(size_t)r * DM + t] + g_vec[(size_t)r * DM + t];
    float s1 = warp_sum(v), s2 = warp_sum(v * v);
    if ((t & 31) == 0) { s_red[t >> 5] = s1; s_red[8 + (t >> 5)] = s2; }
    __syncthreads();
    float S1 = 0.f, S2 = 0.f;
#pragma unroll
    for (int i = 0; i < 8; i++) { S1 += s_red[i]; S2 += s_red[8 + i]; }
    float mean = S1 * (1.0f / 256.0f);
    float var = S2 * (1.0f / 256.0f) - mean * mean;
    g_enc[(size_t)r * DM + t] = (v - mean) * rsqrtf(var + 1e-5f) * g[t] + b[t];
}

__global__ void supmean_kernel() {
    int t = threadIdx.x;
    float s = 0.f;
#pragma unroll
    for (int i = 0; i < NSUP; i++) s += g_enc[(size_t)(NB + i) * DM + t];
    g_supg[t] = s * (1.0f / NSUP);
}

__global__ void rpart_kernel(const float* __restrict__ whh) {
    __shared__ float sg[DM];
    int t = threadIdx.x;
    sg[t] = g_supg[t];
    __syncthreads();
    int n = blockIdx.x * 256 + t;
    const float* row = whh + (size_t)n * LH + DM;
    float s = 0.f;
    for (int k = 0; k < DM; k += 4) {
        float4 w = *(const float4*)(row + k);
        s += w.x * sg[k] + w.y * sg[k + 1] + w.z * sg[k + 2] + w.w * sg[k + 3];
    }
    g_rpart[n] = s;
}

// ------------------- LSTM cell pointwise -------------------
__global__ void __launch_bounds__(256)
cell_kernel(const float* __restrict__ gates, int first) {
    int idx = blockIdx.x * 256 + threadIdx.x;
    int b = idx >> 9, u = idx & 511;
    const float* g = gates + (size_t)b * G4;
    float iv = sigf(g[u]);
    float fv = sigf(g[512 + u]);
    float gv = tanhf(g[1024 + u]);
    float ov = sigf(g[1536 + u]);
    float cp = first ? 0.f : g_c[idx];
    float cn = fv * cp + iv * gv;
    g_c[idx] = cn;
    float hh = ov * tanhf(cn);
    if (u < DM) g_h[(size_t)b * DM + u] = g_enc[(size_t)b * DM + u] + hh;
}

// ------------------- final dot: out[b] = h4[b] . support_g -------------------
__global__ void __launch_bounds__(256)
dot_kernel(float* __restrict__ out) {
    int warp = threadIdx.x >> 5, lane = threadIdx.x & 31;
    int b = blockIdx.x * 8 + warp;
    const float* hp = g_h + (size_t)b * DM;
    float s = 0.f;
#pragma unroll
    for (int k = 0; k < DM; k += 32) s += hp[k + lane] * g_supg[k + lane];
    s = warp_sum(s);
    if (lane == 0) out[b] = s;
}

// ------------------- host -------------------
extern "C" void kernel_launch(void* const* d_in, const int* in_sizes, int n_in,
                              void* d_out, int out_size) {
    const int* qry      = (const int*)d_in[0];
    const int* sup      = (const int*)d_in[1];
    const int* q_l1     = (const int*)d_in[2];
    const int* q_deg_l  = (const int*)d_in[3];
    const int* q_r1     = (const int*)d_in[4];
    const int* q_deg_r  = (const int*)d_in[5];
    const int* s_l1     = (const int*)d_in[6];
    const int* s_deg_l  = (const int*)d_in[7];
    const int* s_r1     = (const int*)d_in[8];
    const int* s_deg_r  = (const int*)d_in[9];
    const float* emb    = (const float*)d_in[10];
    const float* gcn_w_w = (const float*)d_in[11];
    const float* gcn_w_b = (const float*)d_in[12];
    const float* gcn_b   = (const float*)d_in[13];
    const float* g1_w    = (const float*)d_in[14];
    const float* g1_b    = (const float*)d_in[15];
    const float* ln1_g   = (const float*)d_in[16];
    const float* ln1_b   = (const float*)d_in[17];
    const float* g2_w    = (const float*)d_in[18];
    const float* g2_b    = (const float*)d_in[19];
    const float* gate_temp = (const float*)d_in[20];
    const float* se_p1_w = (const float*)d_in[21];
    const float* se_p1_b = (const float*)d_in[22];
    const float* se_p2_w = (const float*)d_in[23];
    const float* se_p2_b = (const float*)d_in[24];
    const float* se_ln_g = (const float*)d_in[25];
    const float* se_ln_b = (const float*)d_in[26];
    const float* w_ih    = (const float*)d_in[27];
    const float* w_hh    = (const float*)d_in[28];
    const float* b_ih    = (const float*)d_in[29];
    const float* b_hh    = (const float*)d_in[30];

    float *vec, *h1, *enc, *xpart, *gates, *h, *bsum, *rpart;
    cudaGetSymbolAddress((void**)&vec, g_vec);
    cudaGetSymbolAddress((void**)&h1, g_h1);
    cudaGetSymbolAddress((void**)&enc, g_enc);
    cudaGetSymbolAddress((void**)&xpart, g_xpart);
    cudaGetSymbolAddress((void**)&gates, g_gates);
    cudaGetSymbolAddress((void**)&h, g_h);
    cudaGetSymbolAddress((void**)&bsum, g_bsum);
    cudaGetSymbolAddress((void**)&rpart, g_rpart);

    // prep: transpose gcn W (128 blocks) + bias sum (8 blocks)
    prep_kernel<<<136, 256>>>(gcn_w_w, b_ih, b_hh);

    // neighbor encoder: q_left | q_right | s_left | s_right
    neighbor_kernel<<<2 * NB + 2 * NSUP, 128>>>(
        qry, sup, q_l1, q_deg_l, q_r1, q_deg_r, s_l1, s_deg_l, s_r1, s_deg_r,
        emb, gcn_w_b, gcn_b, g1_w, g1_b, ln1_g, ln1_b, g2_w, g2_b, gate_temp);

    // support encoder on all 4101 rows
    gemm_kernel<<<dim3(DI / 64, (NROWS + 63) / 64), 256>>>(
        vec, DM, se_p1_w, DM, se_p1_b, nullptr, nullptr, h1, DI, NROWS, DI, DM, 1);
    gemm_kernel<<<dim3(DM / 64, (NROWS + 63) / 64), 256>>>(
        h1, DI, se_p2_w, DI, se_p2_b, nullptr, nullptr, enc, DM, NROWS, DM, DI, 0);
    ln_kernel<<<NROWS, 256>>>(se_ln_g, se_ln_b);

    // support_g + constant r-part of the recurrence
    supmean_kernel<<<1, 256>>>();
    rpart_kernel<<<G4 / 256, 256>>>(w_hh);

    // xpart = query_enc @ w_ih.T + b_ih + b_hh  (constant across steps)
    gemm_kernel<<<dim3(G4 / 64, NB / 64), 256>>>(
        enc, DM, w_ih, DM, bsum, nullptr, nullptr, xpart, G4, NB, G4, DM, 0);

    // step 1: h_r = 0 -> gates = xpart
    cell_kernel<<<(NB * LH) / 256, 256>>>(xpart, 1);

    // steps 2..4: gates = xpart + rpart + h @ Whh[:, :256].T
    for (int s = 0; s < 3; s++) {
        gemm_kernel<<<dim3(G4 / 64, NB / 64), 256>>>(
            h, DM, w_hh, LH, nullptr, xpart, rpart, gates, G4, NB, G4, DM, 0);
        cell_kernel<<<(NB * LH) / 256, 256>>>(gates, 0);
    }

    // out[b] = h4[b] . support_g
    dot_kernel<<<NB / 8, 256>>>((float*)d_out);
}

// round 2
// speedup vs baseline: 1.5105x; 1.5105x over previous
#include <cuda_runtime.h>
#include <cstdint>
#include <math.h>

#define NB 4096
#define NSUP 5
#define NROWS (NB + NSUP)   // 4101
#define ED 128
#define DM 256
#define DI 512
#define LH 512
#define G4 2048
#define PADI 200000
#define MAXK 64
#define TOPK 10

// ------------------- device scratch (static, allocation-free) -------------------
__device__ float g_vec[NROWS * DM];
__device__ float g_h1[NROWS * DI];
__device__ float g_enc[NROWS * DM];
__device__ float g_supg[DM];
__device__ float g_rpart[G4];
__device__ float g_bsum[G4];
__device__ float g_xpart[(size_t)NB * G4];
__device__ float g_gates[(size_t)NB * G4];
__device__ float g_h[(size_t)NB * DM];
__device__ float g_c[(size_t)NB * LH];
__device__ float g_gcnWt[DM * ED];

__device__ __forceinline__ float warp_sum(float v) {
#pragma unroll
    for (int o = 16; o; o >>= 1) v += __shfl_xor_sync(0xffffffffu, v, o);
    return v;
}
__device__ __forceinline__ float sigf(float x) { return 1.0f / (1.0f + expf(-x)); }

// ------------------- prep -------------------
__global__ void prep_kernel(const float* __restrict__ gcn_w_w,
                            const float* __restrict__ b_ih,
                            const float* __restrict__ b_hh) {
    int t = threadIdx.x;
    if (blockIdx.x < 128) {
        int d = blockIdx.x;
        g_gcnWt[t * ED + d] = gcn_w_w[d * DM + t];
    } else {
        int n = (blockIdx.x - 128) * 256 + t;
        g_bsum[n] = b_ih[n] + b_hh[n];
    }
}

// ------------------- neighbor encoder (unchanged, correct) -------------------
__global__ void __launch_bounds__(128)
neighbor_kernel(const int* __restrict__ qry, const int* __restrict__ sup,
                const int* __restrict__ q_l1, const int* __restrict__ q_deg_l,
                const int* __restrict__ q_r1, const int* __restrict__ q_deg_r,
                const int* __restrict__ s_l1, const int* __restrict__ s_deg_l,
                const int* __restrict__ s_r1, const int* __restrict__ s_deg_r,
                const float* __restrict__ emb,
                const float* __restrict__ gcn_w_b, const float* __restrict__ gcn_b,
                const float* __restrict__ g1_w, const float* __restrict__ g1_b,
                const float* __restrict__ ln1_g, const float* __restrict__ ln1_b,
                const float* __restrict__ g2_w, const float* __restrict__ g2_b,
                const float* __restrict__ gate_temp) {
    __shared__ float s_self[ED], s_selfn[ED];
    __shared__ float s_sim[MAXK];
    __shared__ int s_rel[MAXK], s_ent[MAXK];
    __shared__ int s_sel[TOPK], s_pad[TOPK];
    __shared__ float s_concat[TOPK * DM];
    __shared__ float s_agg[ED];
    __shared__ float s_red[8];
    __shared__ float s_sc[2];
    __shared__ int s_nv;

    int blk = blockIdx.x, tid = threadIdx.x;
    const int* conn;
    int selfid, deg;
    float* out;
    if (blk < NB) {
        int b = blk; conn = q_l1 + b * MAXK * 2; deg = q_deg_l[b];
        selfid = qry[b * 2 + 0]; out = g_vec + (size_t)b * DM;
    } else if (blk < 2 * NB) {
        int b = blk - NB; conn = q_r1 + b * MAXK * 2; deg = q_deg_r[b];
        selfid = qry[b * 2 + 1]; out = g_vec + (size_t)b * DM + ED;
    } else if (blk < 2 * NB + NSUP) {
        int i = blk - 2 * NB; conn = s_l1 + i * MAXK * 2; deg = s_deg_l[i];
        selfid = sup[i * 2 + 0]; out = g_vec + (size_t)(NB + i) * DM;
    } else {
        int i = blk - 2 * NB - NSUP; conn = s_r1 + i * MAXK * 2; deg = s_deg_r[i];
        selfid = sup[i * 2 + 1]; out = g_vec + (size_t)(NB + i) * DM + ED;
    }

    float se = emb[(size_t)selfid * ED + tid];
    s_self[tid] = se;
    float ss = warp_sum(se * se);
    if ((tid & 31) == 0) s_red[tid >> 5] = ss;
    __syncthreads();
    if (tid == 0)
        s_sc[0] = 1.0f / fmaxf(sqrtf(s_red[0] + s_red[1] + s_red[2] + s_red[3]), 1e-12f);
    __syncthreads();
    s_selfn[tid] = se * s_sc[0];
    __syncthreads();

    int warp = tid >> 5, lane = tid & 31;
    float4 sn = ((const float4*)s_selfn)[lane];
    for (int j = warp; j < MAXK; j += 4) {
        int rel = conn[j * 2 + 0];
        int ent = conn[j * 2 + 1];
        float4 e = ((const float4*)(emb + (size_t)ent * ED))[lane];
        float dot = e.x * sn.x + e.y * sn.y + e.z * sn.z + e.w * sn.w;
        float sq = e.x * e.x + e.y * e.y + e.z * e.z + e.w * e.w;
        dot = warp_sum(dot);
        sq = warp_sum(sq);
        if (lane == 0) {
            float sim = dot / fmaxf(sqrtf(sq), 1e-12f);
            if (rel == PADI) sim -= 1e9f;
            s_sim[j] = sim; s_rel[j] = rel; s_ent[j] = ent;
        }
    }
    __syncthreads();

    if (tid == 0) {
        float* sv = s_concat;
        for (int j = 0; j < MAXK; j++) sv[j] = s_sim[j];
        int nv = 0;
        for (int t = 0; t < TOPK; t++) {
            int bi = 0; float bvv = sv[0];
            for (int j = 1; j < MAXK; j++)
                if (sv[j] > bvv) { bvv = sv[j]; bi = j; }
            sv[bi] = -3.0e38f;
            s_sel[t] = bi;
            int p = (s_rel[bi] == PADI);
            s_pad[t] = p;
            if (!p) nv++;
        }
        s_nv = nv;
    }
    __syncthreads();

    for (int t = tid; t < TOPK * DM; t += 128) {
        int j = t >> 8, k = t & 255;
        int id = (k < ED) ? s_rel[s_sel[j]] : s_ent[s_sel[j]];
        s_concat[t] = emb[(size_t)id * ED + (k & (ED - 1))];
    }
    __syncthreads();

    float acc[TOPK];
#pragma unroll
    for (int j = 0; j < TOPK; j++) acc[j] = 0.f;
    for (int k0 = 0; k0 < DM; k0 += 8) {
        float w[8];
#pragma unroll
        for (int i = 0; i < 8; i++) w[i] = g_gcnWt[(k0 + i) * ED + tid];
#pragma unroll
        for (int j = 0; j < TOPK; j++) {
            float4 c0 = *(const float4*)&s_concat[j * DM + k0];
            float4 c1 = *(const float4*)&s_concat[j * DM + k0 + 4];
            acc[j] += c0.x * w[0] + c0.y * w[1] + c0.z * w[2] + c0.w * w[3]
                    + c1.x * w[4] + c1.y * w[5] + c1.z * w[6] + c1.w * w[7];
        }
    }
    float bias = gcn_w_b[tid] + gcn_b[tid];
    float agg = 0.f;
#pragma unroll
    for (int j = 0; j < TOPK; j++) {
        float v = acc[j] + bias;
        v = v > 0.f ? v : 0.01f * v;
        if (!s_pad[j]) agg += v;
    }
    agg /= fmaxf((float)s_nv, 1.0f);
    s_agg[tid] = agg;
    __syncthreads();

    float y = 0.f;
    if (tid < 64) {
        const float4* wr = (const float4*)(g1_w + tid * ED);
        const float4* ag = (const float4*)s_agg;
#pragma unroll
        for (int k = 0; k < 32; k++) {
            float4 a = ag[k]; float4 w = wr[k];
            y += a.x * w.x + a.y * w.y + a.z * w.z + a.w * w.w;
        }
        y += g1_b[tid];
    }
    float s1 = warp_sum(tid < 64 ? y : 0.f);
    float s2 = warp_sum(tid < 64 ? y * y : 0.f);
    __syncthreads();
    if ((tid & 31) == 0) { s_red[tid >> 5] = s1; s_red[4 + (tid >> 5)] = s2; }
    __syncthreads();
    float S1 = s_red[0] + s_red[1] + s_red[2] + s_red[3];
    float S2 = s_red[4] + s_red[5] + s_red[6] + s_red[7];
    float mean = S1 * (1.0f / 64.0f);
    float var = S2 * (1.0f / 64.0f) - mean * mean;
    float hv = 0.f;
    if (tid < 64) {
        hv = (y - mean) * rsqrtf(var + 1e-5f) * ln1_g[tid] + ln1_b[tid];
        hv = fmaxf(hv, 0.f);
    }
    float lz = warp_sum(tid < 64 ? hv * g2_w[tid] : 0.f);
    __syncthreads();
    if ((tid & 31) == 0) s_red[tid >> 5] = lz;
    __syncthreads();
    if (tid == 0) {
        float logit = s_red[0] + s_red[1] + s_red[2] + s_red[3] + g2_b[0];
        float temp = fminf(fmaxf(gate_temp[0], 0.1f), 5.0f);
        float gate = 1.0f / (1.0f + expf(-logit / temp));
        if (deg <= 0) gate = 0.f;
        s_sc[1] = gate;
    }
    __syncthreads();
    out[tid] = tanhf(s_self[tid] + s_sc[1] * s_agg[tid]);
}

// ------------------- TF32 tensor-core GEMM: C = A(MxK) * W(NxK)^T -------------------
// 128x128 block tile, BK=16, cp.async double buffer, 8 warps of 64x32.
#define BM 128
#define BN 128
#define BK 16
#define KPAD 20

__device__ __forceinline__ void cp_async16(uint32_t s, const void* g, int sz) {
    asm volatile("cp.async.cg.shared.global [%0], [%1], 16, %2;\n"
                 :: "r"(s), "l"(g), "r"(sz));
}
__device__ __forceinline__ void cp_commit() {
    asm volatile("cp.async.commit_group;\n");
}
__device__ __forceinline__ void cp_wait1() {
    asm volatile("cp.async.wait_group 1;\n");
}
__device__ __forceinline__ void cp_wait0() {
    asm volatile("cp.async.wait_group 0;\n");
}
__device__ __forceinline__ uint32_t tf32_of(float v) {
    uint32_t r;
    asm("cvt.rna.tf32.f32 %0, %1;" : "=r"(r) : "f"(v));
    return r;
}
__device__ __forceinline__ void mma_tf32(float* c, const uint32_t* a, const uint32_t* b) {
    asm volatile(
        "mma.sync.aligned.m16n8k8.row.col.f32.tf32.tf32.f32 "
        "{%0,%1,%2,%3}, {%4,%5,%6,%7}, {%8,%9}, {%0,%1,%2,%3};"
        : "+f"(c[0]), "+f"(c[1]), "+f"(c[2]), "+f"(c[3])
        : "r"(a[0]), "r"(a[1]), "r"(a[2]), "r"(a[3]), "r"(b[0]), "r"(b[1]));
}

__global__ void __launch_bounds__(256, 2)
gemm_tf32(const float* __restrict__ A, int lda,
          const float* __restrict__ W, int ldw,
          const float* __restrict__ bias,
          const float* __restrict__ base,
          const float* __restrict__ rowv,
          float* __restrict__ C, int ldc,
          int M, int N, int K, int act) {
    __shared__ float As[2][BM][KPAD];
    __shared__ float Bs[2][BN][KPAD];

    int tid = threadIdx.x;
    int m0 = blockIdx.y * BM, n0 = blockIdx.x * BN;
    int lane = tid & 31, warp = tid >> 5;
    int wm = warp >> 2, wn = warp & 3;          // 2 x 4 warps
    int r = lane >> 2, cq = lane & 3;

    uint32_t sA = (uint32_t)__cvta_generic_to_shared(&As[0][0][0]);
    uint32_t sB = (uint32_t)__cvta_generic_to_shared(&Bs[0][0][0]);
    const uint32_t bufStrideA = BM * KPAD * 4;
    const uint32_t bufStrideB = BN * KPAD * 4;

    // per-thread staging indices: i in {tid, tid+256}; row=i>>2, k4=(i&3)*4
    int rowA0 = tid >> 2, k4_0 = (tid & 3) << 2;
    int rowA1 = (tid + 256) >> 2, k4_1 = k4_0;  // (i&3) identical for +256

    float c[4][4][4];
#pragma unroll
    for (int i = 0; i < 4; i++)
#pragma unroll
        for (int j = 0; j < 4; j++)
#pragma unroll
            for (int q = 0; q < 4; q++) c[i][j][q] = 0.f;

    int KT = K / BK;

    // ---- issue stage 0 ----
    {
        int k0 = 0;
        int mA0 = m0 + rowA0, mA1 = m0 + rowA1;
        cp_async16(sA + (rowA0 * KPAD + k4_0) * 4, A + (size_t)mA0 * lda + k0 + k4_0, mA0 < M ? 16 : 0);
        cp_async16(sA + (rowA1 * KPAD + k4_1) * 4, A + (size_t)mA1 * lda + k0 + k4_1, mA1 < M ? 16 : 0);
        cp_async16(sB + (rowA0 * KPAD + k4_0) * 4, W + (size_t)(n0 + rowA0) * ldw + k0 + k4_0, 16);
        cp_async16(sB + (rowA1 * KPAD + k4_1) * 4, W + (size_t)(n0 + rowA1) * ldw + k0 + k4_1, 16);
        cp_commit();
    }

    int buf = 0;
    for (int kt = 0; kt < KT; kt++) {
        if (kt + 1 < KT) {
            int k0 = (kt + 1) * BK;
            uint32_t oA = sA + (buf ^ 1) * bufStrideA;
            uint32_t oB = sB + (buf ^ 1) * bufStrideB;
            int mA0 = m0 + rowA0, mA1 = m0 + rowA1;
            cp_async16(oA + (rowA0 * KPAD + k4_0) * 4, A + (size_t)mA0 * lda + k0 + k4_0, mA0 < M ? 16 : 0);
            cp_async16(oA + (rowA1 * KPAD + k4_1) * 4, A + (size_t)mA1 * lda + k0 + k4_1, mA1 < M ? 16 : 0);
            cp_async16(oB + (rowA0 * KPAD + k4_0) * 4, W + (size_t)(n0 + rowA0) * ldw + k0 + k4_0, 16);
            cp_async16(oB + (rowA1 * KPAD + k4_1) * 4, W + (size_t)(n0 + rowA1) * ldw + k0 + k4_1, 16);
            cp_commit();
            cp_wait1();
        } else {
            cp_wait0();
        }
        __syncthreads();

        const float (*Ab)[KPAD] = As[buf];
        const float (*Bb)[KPAD] = Bs[buf];
#pragma unroll
        for (int ks = 0; ks < BK / 8; ks++) {
            int kb = ks * 8;
            uint32_t a[4][4];
#pragma unroll
            for (int am = 0; am < 4; am++) {
                int row = wm * 64 + am * 16 + r;
                a[am][0] = tf32_of(Ab[row][kb + cq]);
                a[am][1] = tf32_of(Ab[row + 8][kb + cq]);
                a[am][2] = tf32_of(Ab[row][kb + cq + 4]);
                a[am][3] = tf32_of(Ab[row + 8][kb + cq + 4]);
            }
            uint32_t b[4][2];
#pragma unroll
            for (int an = 0; an < 4; an++) {
                int nrow = wn * 32 + an * 8 + r;
                b[an][0] = tf32_of(Bb[nrow][kb + cq]);
                b[an][1] = tf32_of(Bb[nrow][kb + cq + 4]);
            }
#pragma unroll
            for (int am = 0; am < 4; am++)
#pragma unroll
                for (int an = 0; an < 4; an++)
                    mma_tf32(c[am][an], a[am], b[an]);
        }
        __syncthreads();
        buf ^= 1;
    }

    // ---- epilogue ----
#pragma unroll
    for (int am = 0; am < 4; am++) {
        int row0 = m0 + wm * 64 + am * 16 + r;
        int row1 = row0 + 8;
#pragma unroll
        for (int an = 0; an < 4; an++) {
            int col = n0 + wn * 32 + an * 8 + cq * 2;
            float add0 = 0.f, add1 = 0.f;
            if (bias) { add0 += bias[col]; add1 += bias[col + 1]; }
            if (rowv) { add0 += rowv[col]; add1 += rowv[col + 1]; }
            if (row0 < M) {
                float v0 = c[am][an][0] + add0;
                float v1 = c[am][an][1] + add1;
                if (base) {
                    v0 += base[(size_t)row0 * ldc + col];
                    v1 += base[(size_t)row0 * ldc + col + 1];
                }
                if (act) { v0 = fmaxf(v0, 0.f); v1 = fmaxf(v1, 0.f); }
                C[(size_t)row0 * ldc + col] = v0;
                C[(size_t)row0 * ldc + col + 1] = v1;
            }
            if (row1 < M) {
                float v2 = c[am][an][2] + add0;
                float v3 = c[am][an][3] + add1;
                if (base) {
                    v2 += base[(size_t)row1 * ldc + col];
                    v3 += base[(size_t)row1 * ldc + col + 1];
                }
                if (act) { v2 = fmaxf(v2, 0.f); v3 = fmaxf(v3, 0.f); }
                C[(size_t)row1 * ldc + col] = v2;
                C[(size_t)row1 * ldc + col + 1] = v3;
            }
        }
    }
}

// ------------------- residual layernorm -------------------
__global__ void __launch_bounds__(256)
ln_kernel(const float* __restrict__ g, const float* __restrict__ b) {
    __shared__ float s_red[16];
    int r = blockIdx.x, t = threadIdx.x;
    float v = g_enc[(size_t)r * DM + t] + g_vec[(size_t)r * DM + t];
    float s1 = warp_sum(v), s2 = warp_sum(v * v);
    if ((t & 31) == 0) { s_red[t >> 5] = s1; s_red[8 + (t >> 5)] = s2; }
    __syncthreads();
    float S1 = 0.f, S2 = 0.f;
#pragma unroll
    for (int i = 0; i < 8; i++) { S1 += s_red[i]; S2 += s_red[8 + i]; }
    float mean = S1 * (1.0f / 256.0f);
    float var = S2 * (1.0f / 256.0f) - mean * mean;
    g_enc[(size_t)r * DM + t] = (v - mean) * rsqrtf(var + 1e-5f) * g[t] + b[t];
}

__global__ void supmean_kernel() {
    int t = threadIdx.x;
    float s = 0.f;
#pragma unroll
    for (int i = 0; i < NSUP; i++) s += g_enc[(size_t)(NB + i) * DM + t];
    g_supg[t] = s * (1.0f / NSUP);
}

__global__ void rpart_kernel(const float* __restrict__ whh) {
    __shared__ float sg[DM];
    int t = threadIdx.x;
    sg[t] = g_supg[t];
    __syncthreads();
    int n = blockIdx.x * 256 + t;
    const float* row = whh + (size_t)n * LH + DM;
    float s = 0.f;
    for (int k = 0; k < DM; k += 4) {
        float4 w = *(const float4*)(row + k);
        s += w.x * sg[k] + w.y * sg[k + 1] + w.z * sg[k + 2] + w.w * sg[k + 3];
    }
    g_rpart[n] = s;
}

// ------------------- LSTM cell pointwise -------------------
__global__ void __launch_bounds__(256)
cell_kernel(const float* __restrict__ gates, int first) {
    int idx = blockIdx.x * 256 + threadIdx.x;
    int b = idx >> 9, u = idx & 511;
    const float* g = gates + (size_t)b * G4;
    float iv = sigf(g[u]);
    float fv = sigf(g[512 + u]);
    float gv = tanhf(g[1024 + u]);
    float ov = sigf(g[1536 + u]);
    float cp = first ? 0.f : g_c[idx];
    float cn = fv * cp + iv * gv;
    g_c[idx] = cn;
    float hh = ov * tanhf(cn);
    if (u < DM) g_h[(size_t)b * DM + u] = g_enc[(size_t)b * DM + u] + hh;
}

// ------------------- final dot -------------------
__global__ void __launch_bounds__(256)
dot_kernel(float* __restrict__ out) {
    int warp = threadIdx.x >> 5, lane = threadIdx.x & 31;
    int b = blockIdx.x * 8 + warp;
    const float* hp = g_h + (size_t)b * DM;
    float s = 0.f;
#pragma unroll
    for (int k = 0; k < DM; k += 32) s += hp[k + lane] * g_supg[k + lane];
    s = warp_sum(s);
    if (lane == 0) out[b] = s;
}

// ------------------- host -------------------
extern "C" void kernel_launch(void* const* d_in, const int* in_sizes, int n_in,
                              void* d_out, int out_size) {
    const int* qry      = (const int*)d_in[0];
    const int* sup      = (const int*)d_in[1];
    const int* q_l1     = (const int*)d_in[2];
    const int* q_deg_l  = (const int*)d_in[3];
    const int* q_r1     = (const int*)d_in[4];
    const int* q_deg_r  = (const int*)d_in[5];
    const int* s_l1     = (const int*)d_in[6];
    const int* s_deg_l  = (const int*)d_in[7];
    const int* s_r1     = (const int*)d_in[8];
    const int* s_deg_r  = (const int*)d_in[9];
    const float* emb    = (const float*)d_in[10];
    const float* gcn_w_w = (const float*)d_in[11];
    const float* gcn_w_b = (const float*)d_in[12];
    const float* gcn_b   = (const float*)d_in[13];
    const float* g1_w    = (const float*)d_in[14];
    const float* g1_b    = (const float*)d_in[15];
    const float* ln1_g   = (const float*)d_in[16];
    const float* ln1_b   = (const float*)d_in[17];
    const float* g2_w    = (const float*)d_in[18];
    const float* g2_b    = (const float*)d_in[19];
    const float* gate_temp = (const float*)d_in[20];
    const float* se_p1_w = (const float*)d_in[21];
    const float* se_p1_b = (const float*)d_in[22];
    const float* se_p2_w = (const float*)d_in[23];
    const float* se_p2_b = (const float*)d_in[24];
    const float* se_ln_g = (const float*)d_in[25];
    const float* se_ln_b = (const float*)d_in[26];
    const float* w_ih    = (const float*)d_in[27];
    const float* w_hh    = (const float*)d_in[28];
    const float* b_ih    = (const float*)d_in[29];
    const float* b_hh    = (const float*)d_in[30];

    float *vec, *h1, *enc, *xpart, *gates, *h, *bsum, *rpart;
    cudaGetSymbolAddress((void**)&vec, g_vec);
    cudaGetSymbolAddress((void**)&h1, g_h1);
    cudaGetSymbolAddress((void**)&enc, g_enc);
    cudaGetSymbolAddress((void**)&xpart, g_xpart);
    cudaGetSymbolAddress((void**)&gates, g_gates);
    cudaGetSymbolAddress((void**)&h, g_h);
    cudaGetSymbolAddress((void**)&bsum, g_bsum);
    cudaGetSymbolAddress((void**)&rpart, g_rpart);

    prep_kernel<<<136, 256>>>(gcn_w_w, b_ih, b_hh);

    neighbor_kernel<<<2 * NB + 2 * NSUP, 128>>>(
        qry, sup, q_l1, q_deg_l, q_r1, q_deg_r, s_l1, s_deg_l, s_r1, s_deg_r,
        emb, gcn_w_b, gcn_b, g1_w, g1_b, ln1_g, ln1_b, g2_w, g2_b, gate_temp);

    // support encoder on all 4101 rows (M=4101 -> 33 row-blocks)
    gemm_tf32<<<dim3(DI / BN, (NROWS + BM - 1) / BM), 256>>>(
        vec, DM, se_p1_w, DM, se_p1_b, nullptr, nullptr, h1, DI, NROWS, DI, DM, 1);
    gemm_tf32<<<dim3(DM / BN, (NROWS + BM - 1) / BM), 256>>>(
        h1, DI, se_p2_w, DI, se_p2_b, nullptr, nullptr, enc, DM, NROWS, DM, DI, 0);
    ln_kernel<<<NROWS, 256>>>(se_ln_g, se_ln_b);

    supmean_kernel<<<1, 256>>>();
    rpart_kernel<<<G4 / 256, 256>>>(w_hh);

    // xpart = query_enc @ w_ih.T + (b_ih + b_hh)
    gemm_tf32<<<dim3(G4 / BN, NB / BM), 256>>>(
        enc, DM, w_ih, DM, bsum, nullptr, nullptr, xpart, G4, NB, G4, DM, 0);

    cell_kernel<<<(NB * LH) / 256, 256>>>(xpart, 1);

    for (int s = 0; s < 3; s++) {
        gemm_tf32<<<dim3(G4 / BN, NB / BM), 256>>>(
            h, DM, w_hh, LH, nullptr, xpart, rpart, gates, G4, NB, G4, DM, 0);
        cell_kernel<<<(NB * LH) / 256, 256>>>(gates, 0);
    }

    dot_kernel<<<NB / 8, 256>>>((float*)d_out);
}